// round 8
// baseline (speedup 1.0000x reference)
#include <cuda_runtime.h>
#include <cstdint>
#include <cstddef>

#define S_LEN 8192
#define HID   768
#define GATE4 3072   // 4*H
#define E_DIM 300
#define V_SZ  100000

typedef unsigned long long ull;

// ---------------- scratch (device globals; no runtime allocation) -----------
__device__ float g_gates_f[(size_t)S_LEN * GATE4];   // ~100MB per direction
__device__ float g_gates_b[(size_t)S_LEN * GATE4];
__device__ float g_h[2][2][HID];                     // [dir][parity][H]
__device__ int   g_cnt[2];                           // per-direction arrival counters

// ---------------- init: reset state each launch -----------------------------
__global__ void init_kernel() {
    int t = threadIdx.x;
    if (t < 2) g_cnt[t] = 0;
    for (int i = t; i < 2 * 2 * HID; i += blockDim.x)
        ((float*)g_h)[i] = 0.f;
}

// ---------------- PTX helpers ------------------------------------------------
__device__ __forceinline__ int ld_acquire_gpu(const int* p) {
    int v;
    asm volatile("ld.acquire.gpu.global.s32 %0, [%1];" : "=r"(v) : "l"(p) : "memory");
    return v;
}
__device__ __forceinline__ void red_release_gpu(int* p, int v) {
    asm volatile("red.release.gpu.global.add.s32 [%0], %1;" :: "l"(p), "r"(v) : "memory");
}
__device__ __forceinline__ void fma2(ull& d, ull a, ull b, ull c) {
    asm("fma.rn.f32x2 %0, %1, %2, %3;" : "=l"(d) : "l"(a), "l"(b), "l"(c));
}

// ---------------- fused gather + input-projection SGEMM ---------------------
// out[s][n] = emb[idx[s]] . W[n] + (b_ih[n]+b_hh[n]); grid (24, 64, 2)
__global__ __launch_bounds__(256) void gemm_gates(
    const int*   __restrict__ idx, int n_idx,
    const float* __restrict__ emb,
    const float* __restrict__ Wf,   const float* __restrict__ Wb,
    const float* __restrict__ bihf, const float* __restrict__ bhhf,
    const float* __restrict__ bihb, const float* __restrict__ bhhb)
{
    __shared__ __align__(16) float As[8][132];
    __shared__ __align__(16) float Bs[8][132];
    __shared__ int sidx[128];

    const int dir = blockIdx.z;
    const float* __restrict__ W   = dir ? Wb   : Wf;
    const float* __restrict__ bih = dir ? bihb : bihf;
    const float* __restrict__ bhh = dir ? bhhb : bhhf;
    float* __restrict__ outg = dir ? g_gates_b : g_gates_f;

    const int tid = threadIdx.x;
    const int m0 = blockIdx.y * 128;
    const int n0 = blockIdx.x * 128;

    if (tid < 128) {
        int ii = m0 + tid;
        if (ii >= n_idx) ii = n_idx - 1;
        if (ii < 0) ii = 0;
        int v = idx[ii];
        v = v < 0 ? 0 : (v >= V_SZ ? V_SZ - 1 : v);
        sidx[tid] = v;
    }
    __syncthreads();

    const int arow = tid >> 1;          // 0..127
    const int acol = (tid & 1) * 4;     // 0 or 4
    const float* arow_p = emb + (size_t)sidx[arow] * E_DIM;   // 1200B row stride
    const float* brow_p = W   + (size_t)(n0 + arow) * E_DIM;

    const int tx = tid & 15;            // N micro
    const int ty = tid >> 4;            // M micro

    float acc[8][8];
    #pragma unroll
    for (int i = 0; i < 8; i++)
        #pragma unroll
        for (int j = 0; j < 8; j++) acc[i][j] = 0.f;

    for (int k0 = 0; k0 < E_DIM; k0 += 8) {     // 38 tiles; last has 4 valid cols
        float4 av, bv;
        if (k0 + acol < E_DIM) {                // full, aligned float4 (300 % 4 == 0)
            av = *(const float4*)(arow_p + k0 + acol);
            bv = *(const float4*)(brow_p + k0 + acol);
        } else {
            av = make_float4(0.f, 0.f, 0.f, 0.f);
            bv = make_float4(0.f, 0.f, 0.f, 0.f);
        }
        As[acol + 0][arow] = av.x; As[acol + 1][arow] = av.y;
        As[acol + 2][arow] = av.z; As[acol + 3][arow] = av.w;
        Bs[acol + 0][arow] = bv.x; Bs[acol + 1][arow] = bv.y;
        Bs[acol + 2][arow] = bv.z; Bs[acol + 3][arow] = bv.w;
        __syncthreads();

        #pragma unroll
        for (int k = 0; k < 8; k++) {
            float4 a0 = *(const float4*)&As[k][ty * 8];
            float4 a1 = *(const float4*)&As[k][ty * 8 + 4];
            float4 b0 = *(const float4*)&Bs[k][tx * 8];
            float4 b1 = *(const float4*)&Bs[k][tx * 8 + 4];
            float a[8] = {a0.x, a0.y, a0.z, a0.w, a1.x, a1.y, a1.z, a1.w};
            float b[8] = {b0.x, b0.y, b0.z, b0.w, b1.x, b1.y, b1.z, b1.w};
            #pragma unroll
            for (int i = 0; i < 8; i++)
                #pragma unroll
                for (int j = 0; j < 8; j++)
                    acc[i][j] = fmaf(a[i], b[j], acc[i][j]);
        }
        __syncthreads();
    }

    float bias[8];
    #pragma unroll
    for (int j = 0; j < 8; j++) {
        const int n = n0 + tx * 8 + j;
        bias[j] = bih[n] + bhh[n];
    }
    #pragma unroll
    for (int i = 0; i < 8; i++) {
        const size_t row = (size_t)(m0 + ty * 8 + i);
        float* op = outg + row * GATE4 + n0 + tx * 8;   // 32B-aligned
        float4 v0, v1;
        v0.x = acc[i][0] + bias[0]; v0.y = acc[i][1] + bias[1];
        v0.z = acc[i][2] + bias[2]; v0.w = acc[i][3] + bias[3];
        v1.x = acc[i][4] + bias[4]; v1.y = acc[i][5] + bias[5];
        v1.z = acc[i][6] + bias[6]; v1.w = acc[i][7] + bias[7];
        *(float4*)(op)     = v0;
        *(float4*)(op + 4) = v1;
    }
}

// ---------------- activations ------------------------------------------------
__device__ __forceinline__ float sigf(float x) {
    return __fdividef(1.f, 1.f + __expf(-x));
}
__device__ __forceinline__ float tanhf_fast(float x) {
    return 1.f - __fdividef(2.f, __expf(2.f * x) + 1.f);
}

// ---------------- persistent recurrence --------------------------------------
// 128 CTAs: [0,64) forward, [64,128) backward. Each CTA owns 12 hidden units =
// 48 gate rows of W_hh, register-resident PACKED f32x2 (72 ull/thread).
// Lane l of each warp handles packed column pairs p = l + 32*j (j=0..11),
// i.e. scalar columns {2p, 2p+1}. fma.rn.f32x2 halves FMA issue count.
__global__ __launch_bounds__(256, 1) void lstm_rec(
    const float* __restrict__ Whhf, const float* __restrict__ Whhb)
{
    const int cta = blockIdx.x;
    const int d   = cta >> 6;
    const int cc  = cta & 63;
    const float* __restrict__ Whh   = d ? Whhb      : Whhf;
    const float* __restrict__ gbase = d ? g_gates_b : g_gates_f;
    const int tid = threadIdx.x;
    const int w = tid >> 5;
    const int l = tid & 31;
    const int u0 = cc * 12;

    // packed weights: row rr = w*6+r -> gate rr/12, unit u0 + rr%12
    ull wreg[6][12];
    #pragma unroll
    for (int r = 0; r < 6; r++) {
        const int rr = w * 6 + r;
        const int grow = (rr / 12) * HID + u0 + (rr % 12);
        const ull* wp = (const ull*)(Whh + (size_t)grow * HID);  // 8B-aligned
        #pragma unroll
        for (int j = 0; j < 12; j++) wreg[r][j] = wp[l + 32 * j];
    }

    __shared__ float rowsum[48];
    __shared__ int sflag;
    if (tid == 0) sflag = 0;
    __syncthreads();
    volatile int* svflag = &sflag;

    float cstate = 0.f;                 // live in threads 0..11
    int* cnt = &g_cnt[d];
    float* hbuf0 = g_h[d][0];
    float* hbuf1 = g_h[d][1];

    for (int t = 1; t <= S_LEN; t++) {
        // prefetch this step's precomputed input gates (independent of h)
        float gi = 0.f, gf2 = 0.f, gg = 0.f, go = 0.f;
        if (tid < 12) {
            const float* gp = gbase + (size_t)(t - 1) * GATE4 + u0 + tid;
            gi  = gp[0];
            gf2 = gp[HID];
            gg  = gp[2 * HID];
            go  = gp[3 * HID];
        }

        // wait until h_{t-1} fully published: warp 0 polls L2, relays via smem
        if (t > 1) {
            const int target = 64 * (t - 1);
            if (w == 0) {
                while (ld_acquire_gpu(cnt) < target) { }
                __threadfence_block();
                if (l == 0) *svflag = t;
            } else {
                while (*svflag < t) { }
                __threadfence_block();
            }
        }

        // matvec: direct L2 loads (f32x2) + packed FFMA2
        const ull* hp = (const ull*)(((t - 1) & 1) ? hbuf1 : hbuf0);
        ull acc2[6] = {0ull, 0ull, 0ull, 0ull, 0ull, 0ull};
        #pragma unroll
        for (int j = 0; j < 12; j++) {
            const ull hv = __ldcg(hp + l + 32 * j);
            #pragma unroll
            for (int r = 0; r < 6; r++)
                fma2(acc2[r], wreg[r][j], hv, acc2[r]);
        }
        float acc[6];
        #pragma unroll
        for (int r = 0; r < 6; r++) {
            acc[r] = __uint_as_float((unsigned)acc2[r]) +
                     __uint_as_float((unsigned)(acc2[r] >> 32));
        }

        // warp butterfly reduce (6 independent trees)
        #pragma unroll
        for (int sh = 16; sh > 0; sh >>= 1)
            #pragma unroll
            for (int r = 0; r < 6; r++)
                acc[r] += __shfl_xor_sync(0xffffffffu, acc[r], sh);

        if (l == 0) {
            #pragma unroll
            for (int r = 0; r < 6; r++) rowsum[w * 6 + r] = acc[r];
        }
        __syncthreads();

        if (tid < 12) {
            const float xi = rowsum[tid]      + gi;
            const float xf = rowsum[12 + tid] + gf2;
            const float xg = rowsum[24 + tid] + gg;
            const float xo = rowsum[36 + tid] + go;
            const float ig = sigf(xi);
            const float fg = sigf(xf);
            const float og = sigf(xo);
            const float gt = tanhf_fast(xg);
            cstate = fmaf(fg, cstate, ig * gt);
            const float hv = og * tanhf_fast(cstate);
            float* hdst = (t & 1) ? hbuf1 : hbuf0;
            hdst[u0 + tid] = hv;
        }
        __syncthreads();                 // h writes ordered before release
        if (tid == 0) red_release_gpu(cnt, 1);
    }
}

// ---------------- final tag projection ---------------------------------------
__global__ void tag_kernel(const float* __restrict__ Wtag,
                           const float* __restrict__ btag,
                           float* __restrict__ out)
{
    const int w = threadIdx.x >> 5;
    const int l = threadIdx.x & 31;
    if (w >= 20) return;
    // final h_T (t=8192) is in parity 0
    const float* hf = g_h[0][0];
    const float* hb = g_h[1][0];
    float s = 0.f;
    #pragma unroll
    for (int j = 0; j < 48; j++) {
        int k = l + 32 * j;            // 0..1535
        float hv = (k < HID) ? hf[k] : hb[k - HID];
        s = fmaf(Wtag[w * (2 * HID) + k], hv, s);
    }
    #pragma unroll
    for (int sh = 16; sh > 0; sh >>= 1)
        s += __shfl_xor_sync(0xffffffffu, s, sh);
    if (l == 0) out[w] = s + btag[w];
}

// ---------------- launch ------------------------------------------------------
extern "C" void kernel_launch(void* const* d_in, const int* in_sizes, int n_in,
                              void* d_out, int out_size)
{
    // Map inputs by element count (all sizes distinct per group):
    //   inpu 8192 | emb 30,000,000 | W_ih 921,600 x2 | W_hh 2,359,296 x2
    //   biases 3072 x4 | W_tag 30,720 | b_tag 20
    int i_inpu = -1, i_emb = -1, i_wt = -1, i_bt = -1;
    int iWih[2] = {-1, -1}, iWhh[2] = {-1, -1}, iB[4] = {-1, -1, -1, -1};
    int nWih = 0, nWhh = 0, nB = 0;
    for (int i = 0; i < n_in; i++) {
        long s = in_sizes[i];
        if      (s == 8192     && i_inpu < 0) i_inpu = i;
        else if (s == 30000000 && i_emb  < 0) i_emb  = i;
        else if (s == 921600   && nWih < 2)   iWih[nWih++] = i;
        else if (s == 2359296  && nWhh < 2)   iWhh[nWhh++] = i;
        else if (s == 3072     && nB < 4)     iB[nB++] = i;
        else if (s == 30720    && i_wt  < 0)  i_wt  = i;
        else if (s == 20       && i_bt  < 0)  i_bt  = i;
    }
    const bool ok = i_inpu >= 0 && i_emb >= 0 && nWih == 2 && nWhh == 2 &&
                    nB == 4 && i_wt >= 0 && i_bt >= 0;
    if (!ok) {
        const int m = n_in - 1;
        #define CLMP(x) ((x) < 0 ? 0 : ((x) > m ? m : (x)))
        i_inpu = CLMP(0); i_emb = CLMP(1);
        iWih[0] = CLMP(2); iWhh[0] = CLMP(3);
        iB[0] = CLMP(4); iB[1] = CLMP(5);
        iWih[1] = CLMP(6); iWhh[1] = CLMP(7);
        iB[2] = CLMP(8); iB[3] = CLMP(9);
        i_wt = CLMP(10); i_bt = CLMP(11);
        #undef CLMP
    }

    const int*   inpu = (const int*)  d_in[i_inpu];
    const float* emb  = (const float*)d_in[i_emb];
    const float* Wihf = (const float*)d_in[iWih[0]];
    const float* Whhf = (const float*)d_in[iWhh[0]];
    const float* Wihb = (const float*)d_in[iWih[1]];
    const float* Whhb = (const float*)d_in[iWhh[1]];
    const float* bihf = (const float*)d_in[iB[0]];
    const float* bhhf = (const float*)d_in[iB[1]];
    const float* bihb = (const float*)d_in[iB[2]];
    const float* bhhb = (const float*)d_in[iB[3]];
    const float* Wtag = (const float*)d_in[i_wt];
    const float* btag = (const float*)d_in[i_bt];
    float* out = (float*)d_out;

    const int n_idx = in_sizes[i_inpu];

    init_kernel<<<1, 256>>>();
    gemm_gates<<<dim3(24, 64, 2), 256>>>(inpu, n_idx, emb, Wihf, Wihb,
                                         bihf, bhhf, bihb, bhhb);
    lstm_rec<<<128, 256>>>(Whhf, Whhb);
    tag_kernel<<<1, 640>>>(Wtag, btag, out);
}

// round 11
// speedup vs baseline: 1.5931x; 1.5931x over previous
#include <cuda_runtime.h>
#include <cstdint>
#include <cstddef>

#define S_LEN 8192
#define HID   768
#define GATE4 3072   // 4*H
#define E_DIM 300
#define V_SZ  100000

typedef unsigned long long ull;

// ---------------- scratch (device globals; no runtime allocation) -----------
__device__ float g_gates_f[(size_t)S_LEN * GATE4];   // ~100MB per direction
__device__ float g_gates_b[(size_t)S_LEN * GATE4];
// versioned hidden state: one 8B word per unit = (tag:u32 << 32) | f32 value
__device__ ull   g_hv[2][2][HID];                    // [dir][parity][unit]

// ---------------- init: reset state each launch -----------------------------
__global__ void init_kernel() {
    int t = threadIdx.x;
    // zero word = (tag 0, value 0.0f):
    //  buf[0] tag 0 is exactly what step t=1 polls for (want = 0)  -> h_0 = 0
    //  buf[1] tag 0 never matches an odd 'want' -> always overwritten first
    for (int i = t; i < 2 * 2 * HID; i += blockDim.x)
        ((ull*)g_hv)[i] = 0ull;
}

// ---------------- PTX helpers ------------------------------------------------
// RELAXED ATOMIC 8B accesses: PTX guarantees single-copy atomicity only for
// morally-strong ops. Weak .cg b64 may be split by ptxas into two 32b halves,
// letting a poll see a fresh tag with a stale value (root cause of R10's
// rel_err=0.159). ld/st.relaxed.gpu are plain L2 accesses + the atomicity
// guarantee the versioned-word protocol requires.
__device__ __forceinline__ ull ld_relaxed_u64(const ull* p) {
    ull v;
    asm volatile("ld.relaxed.gpu.global.b64 %0, [%1];" : "=l"(v) : "l"(p) : "memory");
    return v;
}
__device__ __forceinline__ void st_relaxed_u64(ull* p, ull v) {
    asm volatile("st.relaxed.gpu.global.b64 [%0], %1;" :: "l"(p), "l"(v) : "memory");
}
__device__ __forceinline__ void fma2(ull& d, ull a, ull b, ull c) {
    asm("fma.rn.f32x2 %0, %1, %2, %3;" : "=l"(d) : "l"(a), "l"(b), "l"(c));
}

// ---------------- fused gather + input-projection SGEMM ---------------------
// out[s][n] = emb[idx[s]] . W[n] + (b_ih[n]+b_hh[n]); grid (24, 64, 2)
__global__ __launch_bounds__(256) void gemm_gates(
    const int*   __restrict__ idx, int n_idx,
    const float* __restrict__ emb,
    const float* __restrict__ Wf,   const float* __restrict__ Wb,
    const float* __restrict__ bihf, const float* __restrict__ bhhf,
    const float* __restrict__ bihb, const float* __restrict__ bhhb)
{
    __shared__ __align__(16) float As[8][132];
    __shared__ __align__(16) float Bs[8][132];
    __shared__ int sidx[128];

    const int dir = blockIdx.z;
    const float* __restrict__ W   = dir ? Wb   : Wf;
    const float* __restrict__ bih = dir ? bihb : bihf;
    const float* __restrict__ bhh = dir ? bhhb : bhhf;
    float* __restrict__ outg = dir ? g_gates_b : g_gates_f;

    const int tid = threadIdx.x;
    const int m0 = blockIdx.y * 128;
    const int n0 = blockIdx.x * 128;

    if (tid < 128) {
        int ii = m0 + tid;
        if (ii >= n_idx) ii = n_idx - 1;
        if (ii < 0) ii = 0;
        int v = idx[ii];
        v = v < 0 ? 0 : (v >= V_SZ ? V_SZ - 1 : v);
        sidx[tid] = v;
    }
    __syncthreads();

    const int arow = tid >> 1;          // 0..127
    const int acol = (tid & 1) * 4;     // 0 or 4
    const float* arow_p = emb + (size_t)sidx[arow] * E_DIM;   // 1200B row stride
    const float* brow_p = W   + (size_t)(n0 + arow) * E_DIM;

    const int tx = tid & 15;            // N micro
    const int ty = tid >> 4;            // M micro

    float acc[8][8];
    #pragma unroll
    for (int i = 0; i < 8; i++)
        #pragma unroll
        for (int j = 0; j < 8; j++) acc[i][j] = 0.f;

    for (int k0 = 0; k0 < E_DIM; k0 += 8) {     // 38 tiles; last has 4 valid cols
        float4 av, bv;
        if (k0 + acol < E_DIM) {                // aligned float4 (300 % 4 == 0)
            av = *(const float4*)(arow_p + k0 + acol);
            bv = *(const float4*)(brow_p + k0 + acol);
        } else {
            av = make_float4(0.f, 0.f, 0.f, 0.f);
            bv = make_float4(0.f, 0.f, 0.f, 0.f);
        }
        As[acol + 0][arow] = av.x; As[acol + 1][arow] = av.y;
        As[acol + 2][arow] = av.z; As[acol + 3][arow] = av.w;
        Bs[acol + 0][arow] = bv.x; Bs[acol + 1][arow] = bv.y;
        Bs[acol + 2][arow] = bv.z; Bs[acol + 3][arow] = bv.w;
        __syncthreads();

        #pragma unroll
        for (int k = 0; k < 8; k++) {
            float4 a0 = *(const float4*)&As[k][ty * 8];
            float4 a1 = *(const float4*)&As[k][ty * 8 + 4];
            float4 b0 = *(const float4*)&Bs[k][tx * 8];
            float4 b1 = *(const float4*)&Bs[k][tx * 8 + 4];
            float a[8] = {a0.x, a0.y, a0.z, a0.w, a1.x, a1.y, a1.z, a1.w};
            float b[8] = {b0.x, b0.y, b0.z, b0.w, b1.x, b1.y, b1.z, b1.w};
            #pragma unroll
            for (int i = 0; i < 8; i++)
                #pragma unroll
                for (int j = 0; j < 8; j++)
                    acc[i][j] = fmaf(a[i], b[j], acc[i][j]);
        }
        __syncthreads();
    }

    float bias[8];
    #pragma unroll
    for (int j = 0; j < 8; j++) {
        const int n = n0 + tx * 8 + j;
        bias[j] = bih[n] + bhh[n];
    }
    #pragma unroll
    for (int i = 0; i < 8; i++) {
        const size_t row = (size_t)(m0 + ty * 8 + i);
        float* op = outg + row * GATE4 + n0 + tx * 8;
        float4 v0, v1;
        v0.x = acc[i][0] + bias[0]; v0.y = acc[i][1] + bias[1];
        v0.z = acc[i][2] + bias[2]; v0.w = acc[i][3] + bias[3];
        v1.x = acc[i][4] + bias[4]; v1.y = acc[i][5] + bias[5];
        v1.z = acc[i][6] + bias[6]; v1.w = acc[i][7] + bias[7];
        *(float4*)(op)     = v0;
        *(float4*)(op + 4) = v1;
    }
}

// ---------------- activations ------------------------------------------------
__device__ __forceinline__ float sigf(float x) {
    return __fdividef(1.f, 1.f + __expf(-x));
}
__device__ __forceinline__ float tanhf_fast(float x) {
    return 1.f - __fdividef(2.f, __expf(2.f * x) + 1.f);
}

// ---------------- persistent recurrence --------------------------------------
// 128 CTAs: [0,64) forward, [64,128) backward. Each CTA owns 12 hidden units =
// 48 gate rows of W_hh, register-resident packed f32x2.
// Sync: versioned data words. h unit u at step t is published as ONE relaxed
// 8B store of (tag=t | f32). Consumers poll the words they need until
// tag == t-1 — a single L2 round trip replaces counter+atomic+relay+load.
// WAR safety (depth-2 buffers): writing h_t requires having read all of
// h_{t-1}, which requires every CTA published h_{t-1}, which happens after
// every CTA finished reading h_{t-2} from buf[t&1]. Max inter-CTA skew = 1
// step, so tags are never overwritten before being observed.
__global__ __launch_bounds__(256, 1) void lstm_rec(
    const float* __restrict__ Whhf, const float* __restrict__ Whhb)
{
    const int cta = blockIdx.x;
    const int d   = cta >> 6;
    const int cc  = cta & 63;
    const float* __restrict__ Whh   = d ? Whhb      : Whhf;
    const float* __restrict__ gbase = d ? g_gates_b : g_gates_f;
    const int tid = threadIdx.x;
    const int w = tid >> 5;
    const int l = tid & 31;
    const int u0 = cc * 12;

    // packed weights: row rr = w*6+r -> gate rr/12, unit u0 + rr%12
    ull wreg[6][12];
    #pragma unroll
    for (int r = 0; r < 6; r++) {
        const int rr = w * 6 + r;
        const int grow = (rr / 12) * HID + u0 + (rr % 12);
        const ull* wp = (const ull*)(Whh + (size_t)grow * HID);  // 8B-aligned
        #pragma unroll
        for (int j = 0; j < 12; j++) wreg[r][j] = wp[l + 32 * j];
    }

    __shared__ __align__(16) float hsh[HID];
    __shared__ float rowsum[48];

    float cstate = 0.f;                 // live in threads 0..11
    ull* hbuf0 = g_hv[d][0];
    ull* hbuf1 = g_hv[d][1];

    for (int t = 1; t <= S_LEN; t++) {
        // prefetch this step's precomputed input gates (overlaps the poll)
        float gi = 0.f, gf2 = 0.f, gg = 0.f, go = 0.f;
        if (tid < 12) {
            const float* gp = gbase + (size_t)(t - 1) * GATE4 + u0 + tid;
            gi  = gp[0];
            gf2 = gp[HID];
            gg  = gp[2 * HID];
            go  = gp[3 * HID];
        }

        // poll + stage h_{t-1}: each thread owns 3 versioned words
        const ull* hsrc = ((t - 1) & 1) ? hbuf1 : hbuf0;
        const unsigned want = (unsigned)(t - 1);
        ull v0 = ld_relaxed_u64(hsrc + tid);
        ull v1 = ld_relaxed_u64(hsrc + tid + 256);
        ull v2 = ld_relaxed_u64(hsrc + tid + 512);
        while ((unsigned)(v0 >> 32) != want) v0 = ld_relaxed_u64(hsrc + tid);
        while ((unsigned)(v1 >> 32) != want) v1 = ld_relaxed_u64(hsrc + tid + 256);
        while ((unsigned)(v2 >> 32) != want) v2 = ld_relaxed_u64(hsrc + tid + 512);
        hsh[tid]       = __uint_as_float((unsigned)v0);
        hsh[tid + 256] = __uint_as_float((unsigned)v1);
        hsh[tid + 512] = __uint_as_float((unsigned)v2);
        __syncthreads();

        // matvec: packed pairs from smem + FFMA2
        const ull* hp = (const ull*)hsh;
        ull acc2[6] = {0ull, 0ull, 0ull, 0ull, 0ull, 0ull};
        #pragma unroll
        for (int j = 0; j < 12; j++) {
            const ull hv = hp[l + 32 * j];       // LDS.64
            #pragma unroll
            for (int r = 0; r < 6; r++)
                fma2(acc2[r], wreg[r][j], hv, acc2[r]);
        }
        float acc[6];
        #pragma unroll
        for (int r = 0; r < 6; r++) {
            acc[r] = __uint_as_float((unsigned)acc2[r]) +
                     __uint_as_float((unsigned)(acc2[r] >> 32));
        }

        // warp butterfly reduce (6 independent trees)
        #pragma unroll
        for (int sh = 16; sh > 0; sh >>= 1)
            #pragma unroll
            for (int r = 0; r < 6; r++)
                acc[r] += __shfl_xor_sync(0xffffffffu, acc[r], sh);

        if (l == 0) {
            #pragma unroll
            for (int r = 0; r < 6; r++) rowsum[w * 6 + r] = acc[r];
        }
        __syncthreads();

        if (tid < 12) {
            const float xi = rowsum[tid]      + gi;
            const float xf = rowsum[12 + tid] + gf2;
            const float xg = rowsum[24 + tid] + gg;
            const float xo = rowsum[36 + tid] + go;
            const float ig = sigf(xi);
            const float fg = sigf(xf);
            const float og = sigf(xo);
            const float gt = tanhf_fast(xg);
            cstate = fmaf(fg, cstate, ig * gt);
            const float hv = og * tanhf_fast(cstate);
            // publish: one ATOMIC (relaxed) 8B word carries value + tag
            ull* hdst = ((t & 1) ? hbuf1 : hbuf0) + u0 + tid;
            st_relaxed_u64(hdst, ((ull)(unsigned)t << 32) | __float_as_uint(hv));
        }
        // no trailing barrier needed: next staging only writes hsh after its
        // poll succeeds, and every warp already passed the rowsum barrier
    }
}

// ---------------- final tag projection ---------------------------------------
__global__ void tag_kernel(const float* __restrict__ Wtag,
                           const float* __restrict__ btag,
                           float* __restrict__ out)
{
    const int w = threadIdx.x >> 5;
    const int l = threadIdx.x & 31;
    if (w >= 20) return;
    // final h_T (t=8192, even) is in parity 0; value = low 32 bits
    const ull* hf = g_hv[0][0];
    const ull* hb = g_hv[1][0];
    float s = 0.f;
    #pragma unroll
    for (int j = 0; j < 48; j++) {
        int k = l + 32 * j;            // 0..1535
        ull word = (k < HID) ? hf[k] : hb[k - HID];
        float hv = __uint_as_float((unsigned)word);
        s = fmaf(Wtag[w * (2 * HID) + k], hv, s);
    }
    #pragma unroll
    for (int sh = 16; sh > 0; sh >>= 1)
        s += __shfl_xor_sync(0xffffffffu, s, sh);
    if (l == 0) out[w] = s + btag[w];
}

// ---------------- launch ------------------------------------------------------
extern "C" void kernel_launch(void* const* d_in, const int* in_sizes, int n_in,
                              void* d_out, int out_size)
{
    // Map inputs by element count (all sizes distinct per group):
    //   inpu 8192 | emb 30,000,000 | W_ih 921,600 x2 | W_hh 2,359,296 x2
    //   biases 3072 x4 | W_tag 30,720 | b_tag 20
    int i_inpu = -1, i_emb = -1, i_wt = -1, i_bt = -1;
    int iWih[2] = {-1, -1}, iWhh[2] = {-1, -1}, iB[4] = {-1, -1, -1, -1};
    int nWih = 0, nWhh = 0, nB = 0;
    for (int i = 0; i < n_in; i++) {
        long s = in_sizes[i];
        if      (s == 8192     && i_inpu < 0) i_inpu = i;
        else if (s == 30000000 && i_emb  < 0) i_emb  = i;
        else if (s == 921600   && nWih < 2)   iWih[nWih++] = i;
        else if (s == 2359296  && nWhh < 2)   iWhh[nWhh++] = i;
        else if (s == 3072     && nB < 4)     iB[nB++] = i;
        else if (s == 30720    && i_wt  < 0)  i_wt  = i;
        else if (s == 20       && i_bt  < 0)  i_bt  = i;
    }
    const bool ok = i_inpu >= 0 && i_emb >= 0 && nWih == 2 && nWhh == 2 &&
                    nB == 4 && i_wt >= 0 && i_bt >= 0;
    if (!ok) {
        const int m = n_in - 1;
        #define CLMP(x) ((x) < 0 ? 0 : ((x) > m ? m : (x)))
        i_inpu = CLMP(0); i_emb = CLMP(1);
        iWih[0] = CLMP(2); iWhh[0] = CLMP(3);
        iB[0] = CLMP(4); iB[1] = CLMP(5);
        iWih[1] = CLMP(6); iWhh[1] = CLMP(7);
        iB[2] = CLMP(8); iB[3] = CLMP(9);
        i_wt = CLMP(10); i_bt = CLMP(11);
        #undef CLMP
    }

    const int*   inpu = (const int*)  d_in[i_inpu];
    const float* emb  = (const float*)d_in[i_emb];
    const float* Wihf = (const float*)d_in[iWih[0]];
    const float* Whhf = (const float*)d_in[iWhh[0]];
    const float* Wihb = (const float*)d_in[iWih[1]];
    const float* Whhb = (const float*)d_in[iWhh[1]];
    const float* bihf = (const float*)d_in[iB[0]];
    const float* bhhf = (const float*)d_in[iB[1]];
    const float* bihb = (const float*)d_in[iB[2]];
    const float* bhhb = (const float*)d_in[iB[3]];
    const float* Wtag = (const float*)d_in[i_wt];
    const float* btag = (const float*)d_in[i_bt];
    float* out = (float*)d_out;

    const int n_idx = in_sizes[i_inpu];

    init_kernel<<<1, 256>>>();
    gemm_gates<<<dim3(24, 64, 2), 256>>>(inpu, n_idx, emb, Wihf, Wihb,
                                         bihf, bhhf, bihb, bhhb);
    lstm_rec<<<128, 256>>>(Whhf, Whhb);
    tag_kernel<<<1, 640>>>(Wtag, btag, out);
}